// round 14
// baseline (speedup 1.0000x reference)
#include <cuda_runtime.h>

// Fixed problem shape
#define BB 4
#define CC 19
#define HH 256
#define WW 256
#define HW (HH * WW)
#define CHW (CC * HW)
#define RAD 10
#define TS 32
#define EW (TS + 2 * RAD)   // 52

// Scratch (device globals). NO contended used-result atomics anywhere.
__device__ float g_ent[BB * HW];
__device__ float g_kl[BB * HW];
__device__ unsigned char g_fg[BB * HW];
__device__ float g_entpart[BB * 256];  // per-K1-block entropy max (unique slots)
__device__ float4 g_part[BB * 64];     // per-K2-block partial sums (unique slots)
__device__ unsigned int g_done1[32];   // level-1 counters (8 blocks each)
__device__ unsigned int g_done2;       // level-2 counter (32 winners)

// ---------------------------------------------------------------------------
// K1: 1 pixel/thread, coalesced, LTS-bound. Block entropy max -> unique STG.
// ---------------------------------------------------------------------------
__global__ void __launch_bounds__(256) k1_channelwise(
    const float* __restrict__ student, const float* __restrict__ teacher)
{
    const int b = blockIdx.y;
    const int p = blockIdx.x * 256 + threadIdx.x;
    const size_t base = (size_t)b * CHW + p;

    float Z = 0.f, S = 0.f, Tt = 0.f, Zs = 0.f;
    float t0, mx = -1e30f;
#pragma unroll
    for (int c = 0; c < CC; c++) {
        float tv = __ldg(teacher + base + (size_t)c * HW) * 0.25f;
        float sv = __ldg(student + base + (size_t)c * HW) * 0.25f;
        float e = __expf(tv);
        Z += e;
        S = fmaf(e, tv, S);
        Tt = fmaf(e, sv, Tt);
        Zs += __expf(sv);
        if (c == 0) t0 = tv;
        else        mx = fmaxf(mx, tv);
    }
    const float lZ = __logf(Z);
    const float ent = lZ - S / Z;
    const float kl = (S - Tt) / Z - lZ + __logf(Zs);

    const int idx = b * HW + p;
    g_ent[idx] = ent;
    g_kl[idx] = kl;
    g_fg[idx] = (mx > t0) ? 1 : 0;   // argmax != 0 (ties -> class 0)

    // block entropy max -> unique slot (plain store, no atomic)
    float entm = ent;
#pragma unroll
    for (int o = 16; o > 0; o >>= 1)
        entm = fmaxf(entm, __shfl_xor_sync(0xFFFFFFFF, entm, o));
    __shared__ float smax[8];
    if ((threadIdx.x & 31) == 0) smax[threadIdx.x >> 5] = entm;
    __syncthreads();
    if (threadIdx.x == 0) {
        float m = smax[0];
#pragma unroll
        for (int w = 1; w < 8; w++) m = fmaxf(m, smax[w]);
        g_entpart[b * 256 + blockIdx.x] = m;
    }
}

// ---------------------------------------------------------------------------
// K2: bounded EDT + weights (R7 proven body). Tail rebuilt: unique-slot
// partials (STG), two-level done counters, elected last block does the final
// reduction in-block and resets the counters for the next graph replay.
// ---------------------------------------------------------------------------
__global__ void __launch_bounds__(1024) k2_edt_weights(float* __restrict__ out)
{
    const int b   = blockIdx.y;
    const int gid = b * 64 + blockIdx.x;   // 0..255
    const int i0  = (blockIdx.x >> 3) * TS;
    const int j0  = (blockIdx.x & 7) * TS;
    const int tid = threadIdx.x;
    const int ty  = tid >> 5;              // tile row 0..31
    const int tx  = tid & 31;              // tile col 0..31

    // prefetch ent/kl (coalesced; L2-resident) — starts latency early
    const int pidx = b * HW + (i0 + ty) * WW + j0 + tx;
    const float entv = __ldg(g_ent + pidx);
    const float klv  = __ldg(g_kl + pidx);

    __shared__ unsigned char sfg[EW][56];  // fg halo: col cc = global j0-12+cc
    __shared__ unsigned char svv[TS][56];  // vertical min-d^2

    // fg halo: 52 rows x 14 aligned u32 words (single step, tid < 728)
    if (tid < EW * 14) {
        int r = tid / 14, k = tid - r * 14;
        int gi = i0 - RAD + r;
        int g0 = j0 - 12 + 4 * k;          // j0 % 32 == 0 -> g0 % 4 == 0
        unsigned int word = 0;
        if (gi >= 0 && gi < HH) {
            const unsigned char* rowp = g_fg + b * HW + gi * WW;
            if (g0 >= 0 && g0 + 3 < WW) {
                word = *(const unsigned int*)(rowp + g0);
            } else {
#pragma unroll
                for (int bb = 0; bb < 4; bb++) {
                    int gj = g0 + bb;
                    if (gj >= 0 && gj < WW)
                        word |= (unsigned int)rowp[gj] << (8 * bb);
                }
            }
        }
        *(unsigned int*)&sfg[r][4 * k] = word;
    }
    __syncthreads();

    // vertical 21-tap min, byte SIMD (term = 200 - fg*(200-d^2)), 2 chains
    if (tid < TS * 14) {
        int r = tid / 14, wc = (tid - r * 14) * 4;
        unsigned int va = 0xC8C8C8C8u, vb = 0xC8C8C8C8u;
#pragma unroll
        for (int dr = 0; dr < 21; dr += 2) {
            unsigned int f4 = *(const unsigned int*)&sfg[r + dr][wc];
            int d = dr - RAD;
            va = __vminu4(va, 0xC8C8C8C8u - f4 * (unsigned int)(200 - d * d));
        }
#pragma unroll
        for (int dr = 1; dr < 21; dr += 2) {
            unsigned int f4 = *(const unsigned int*)&sfg[r + dr][wc];
            int d = dr - RAD;
            vb = __vminu4(vb, 0xC8C8C8C8u - f4 * (unsigned int)(200 - d * d));
        }
        *(unsigned int*)&svv[r][wc] = __vminu4(va, vb);
    }
    __syncthreads();

    // horizontal 21-tap min: independent byte-LDS, 3 split chains
    // pixel col tx -> smem cc = tx+12; taps tx+2 .. tx+22
    int m0 = 300, m1 = 300, m2 = 300;
#pragma unroll
    for (int s = 0; s < 7; s++) {
        int dd = s - RAD;
        m0 = min(m0, dd * dd + (int)svv[ty][tx + 2 + s]);
    }
#pragma unroll
    for (int s = 7; s < 14; s++) {
        int dd = s - RAD;
        m1 = min(m1, dd * dd + (int)svv[ty][tx + 2 + s]);
    }
#pragma unroll
    for (int s = 14; s < 21; s++) {
        int dd = s - RAD;
        m2 = min(m2, dd * dd + (int)svv[ty][tx + 2 + s]);
    }
    const int d2 = min(m0, min(m1, m2));

    // base weight; conf = 1 - 0.9*ent/Em is linear in ent -> accumulate
    // A=Σbw·kl, B=Σbw·kl·ent, C=Σbw, D=Σbw·ent; Em applied at finalize.
    float a0 = 0.f, a1 = 0.f, a2 = 0.f, a3 = 0.f;
    if (d2 <= RAD * RAD) {
        float wd = __expf((float)d2 * (-1.0f / 50.0f));   // 2*sigma^2 = 50
        float bnd = 0.f;
        if (sfg[ty + RAD][tx + 12]) {
            bool er = sfg[ty + RAD - 1][tx + 12] && sfg[ty + RAD + 1][tx + 12]
                   && sfg[ty + RAD][tx + 11] && sfg[ty + RAD][tx + 13];
            if (!er) bnd = 1.f;
        }
        float bw = wd * (1.f + bnd);
        a0 = bw * klv;
        a1 = bw * klv * entv;
        a2 = bw;
        a3 = bw * entv;
    }

    // block reduce 4 sums
#pragma unroll
    for (int o = 16; o > 0; o >>= 1) {
        a0 += __shfl_xor_sync(0xFFFFFFFF, a0, o);
        a1 += __shfl_xor_sync(0xFFFFFFFF, a1, o);
        a2 += __shfl_xor_sync(0xFFFFFFFF, a2, o);
        a3 += __shfl_xor_sync(0xFFFFFFFF, a3, o);
    }
    __shared__ float red[4][32];
    if ((tid & 31) == 0) {
        red[0][tid >> 5] = a0; red[1][tid >> 5] = a1;
        red[2][tid >> 5] = a2; red[3][tid >> 5] = a3;
    }
    __syncthreads();

    __shared__ int s_fin;
    if (tid < 32) {
        float s0 = red[0][tid], s1 = red[1][tid], s2 = red[2][tid], s3 = red[3][tid];
#pragma unroll
        for (int o = 16; o > 0; o >>= 1) {
            s0 += __shfl_xor_sync(0xFFFFFFFF, s0, o);
            s1 += __shfl_xor_sync(0xFFFFFFFF, s1, o);
            s2 += __shfl_xor_sync(0xFFFFFFFF, s2, o);
            s3 += __shfl_xor_sync(0xFFFFFFFF, s3, o);
        }
        if (tid == 0) {
            g_part[gid] = make_float4(s0, s1, s2, s3);   // unique slot, no atomic
            __threadfence();                             // publish before counting
            s_fin = 0;
            unsigned int a = atomicAdd(&g_done1[gid >> 3], 1u);  // <=8 per address
            if (a == 7u) {
                unsigned int c = atomicAdd(&g_done2, 1u);        // 32 total
                if (c == 31u) s_fin = 1;
            }
        }
    }
    __syncthreads();

    // ---- elected last block: final reduction + output + counter reset ----
    if (s_fin) {
        __threadfence();   // acquire (flushes L1D; all partials are visible)

        // per-image entropy max over 1024 K1 partials (tid -> g_entpart[tid]);
        // slots b*256..b*256+255 -> warps 8b..8b+7 (each warp single-image)
        float v = g_entpart[tid];
#pragma unroll
        for (int o = 16; o > 0; o >>= 1)
            v = fmaxf(v, __shfl_xor_sync(0xFFFFFFFF, v, o));
        __shared__ float sEm[32];
        if ((tid & 31) == 0) sEm[tid >> 5] = v;
        __syncthreads();
        __shared__ float em[BB];
        if (tid < BB) {
            float m = sEm[tid * 8];
#pragma unroll
            for (int k = 1; k < 8; k++) m = fmaxf(m, sEm[tid * 8 + k]);
            em[tid] = m;
        }

        // sum 256 partial float4s; warp w (0..7) covers one half-image
        __shared__ double sacc[8][4];
        if (tid < 256) {
            float4 p = g_part[tid];
            float b0 = p.x, b1 = p.y, b2 = p.z, b3 = p.w;
#pragma unroll
            for (int o = 16; o > 0; o >>= 1) {
                b0 += __shfl_xor_sync(0xFFFFFFFF, b0, o);
                b1 += __shfl_xor_sync(0xFFFFFFFF, b1, o);
                b2 += __shfl_xor_sync(0xFFFFFFFF, b2, o);
                b3 += __shfl_xor_sync(0xFFFFFFFF, b3, o);
            }
            if ((tid & 31) == 0) {
                sacc[tid >> 5][0] = (double)b0;
                sacc[tid >> 5][1] = (double)b1;
                sacc[tid >> 5][2] = (double)b2;
                sacc[tid >> 5][3] = (double)b3;
            }
        }
        __syncthreads();

        if (tid == 0) {
            double num = 0.0, den = 0.0;
#pragma unroll
            for (int bb = 0; bb < BB; bb++) {
                double A = sacc[2 * bb][0] + sacc[2 * bb + 1][0];
                double Bm = sacc[2 * bb][1] + sacc[2 * bb + 1][1];
                double Cc = sacc[2 * bb][2] + sacc[2 * bb + 1][2];
                double D = sacc[2 * bb][3] + sacc[2 * bb + 1][3];
                double Em = (double)em[bb] + 1e-8;
                num += A - 0.9 * Bm / Em;
                den += Cc - 0.9 * D / Em;
            }
            out[0] = (float)(16.0 * num / (den + 1e-8));
            g_done2 = 0u;                  // reset for next graph replay
        }
        if (tid < 32) g_done1[tid] = 0u;
    }
}

extern "C" void kernel_launch(void* const* d_in, const int* in_sizes, int n_in,
                              void* d_out, int out_size)
{
    const float* student = (const float*)d_in[0];
    const float* teacher = (const float*)d_in[1];
    float* out = (float*)d_out;

    k1_channelwise<<<dim3(HW / 256, BB), 256>>>(student, teacher);
    k2_edt_weights<<<dim3(64, BB), 1024>>>(out);
}

// round 15
// speedup vs baseline: 1.0845x; 1.0845x over previous
#include <cuda_runtime.h>

// Fixed problem shape
#define BB 4
#define CC 19
#define HH 256
#define WW 256
#define HW (HH * WW)
#define CHW (CC * HW)
#define RAD 10
#define TS 32
#define EW (TS + 2 * RAD)   // 52

// Scratch (device globals). NO contended used-result atomics anywhere.
__device__ float g_ent[BB * HW];
__device__ float g_kl[BB * HW];
__device__ unsigned char g_fg[BB * HW];
__device__ float g_entpart[BB * 256];  // per-K1-block entropy max (unique slots)
__device__ float4 g_part[BB * 64];     // per-K2-block partial sums (unique slots)
__device__ unsigned int g_done1[32];   // level-1 counters (8 blocks each)
__device__ unsigned int g_done2;       // level-2 counter (32 winners)

// ---------------------------------------------------------------------------
// K1: 1 pixel/thread, coalesced, LTS-bound. Block entropy max -> unique STG.
// ---------------------------------------------------------------------------
__global__ void __launch_bounds__(256) k1_channelwise(
    const float* __restrict__ student, const float* __restrict__ teacher)
{
    const int b = blockIdx.y;
    const int p = blockIdx.x * 256 + threadIdx.x;
    const size_t base = (size_t)b * CHW + p;

    float Z = 0.f, S = 0.f, Tt = 0.f, Zs = 0.f;
    float t0, mx = -1e30f;
#pragma unroll
    for (int c = 0; c < CC; c++) {
        float tv = __ldg(teacher + base + (size_t)c * HW) * 0.25f;
        float sv = __ldg(student + base + (size_t)c * HW) * 0.25f;
        float e = __expf(tv);
        Z += e;
        S = fmaf(e, tv, S);
        Tt = fmaf(e, sv, Tt);
        Zs += __expf(sv);
        if (c == 0) t0 = tv;
        else        mx = fmaxf(mx, tv);
    }
    const float lZ = __logf(Z);
    const float ent = lZ - S / Z;
    const float kl = (S - Tt) / Z - lZ + __logf(Zs);

    const int idx = b * HW + p;
    g_ent[idx] = ent;
    g_kl[idx] = kl;
    g_fg[idx] = (mx > t0) ? 1 : 0;   // argmax != 0 (ties -> class 0)

    // block entropy max -> unique slot (plain store, no atomic)
    float entm = ent;
#pragma unroll
    for (int o = 16; o > 0; o >>= 1)
        entm = fmaxf(entm, __shfl_xor_sync(0xFFFFFFFF, entm, o));
    __shared__ float smax[8];
    if ((threadIdx.x & 31) == 0) smax[threadIdx.x >> 5] = entm;
    __syncthreads();
    if (threadIdx.x == 0) {
        float m = smax[0];
#pragma unroll
        for (int w = 1; w < 8; w++) m = fmaxf(m, smax[w]);
        g_entpart[b * 256 + blockIdx.x] = m;
    }
}

// ---------------------------------------------------------------------------
// K2: bounded EDT + weights (R7 proven body, 32-reg / 2-CTA-per-SM profile
// ENFORCED by __launch_bounds__(1024,2)). Tail: unique-slot STG partials +
// two-level counters; elected last block finalizes (spills under the reg cap,
// executed once — negligible).
// ---------------------------------------------------------------------------
__global__ void __launch_bounds__(1024, 2) k2_edt_weights(float* __restrict__ out)
{
    const int b   = blockIdx.y;
    const int gid = b * 64 + blockIdx.x;   // 0..255
    const int i0  = (blockIdx.x >> 3) * TS;
    const int j0  = (blockIdx.x & 7) * TS;
    const int tid = threadIdx.x;
    const int ty  = tid >> 5;              // tile row 0..31
    const int tx  = tid & 31;              // tile col 0..31

    // prefetch ent/kl (coalesced; L2-resident) — starts latency early
    const int pidx = b * HW + (i0 + ty) * WW + j0 + tx;
    const float entv = __ldg(g_ent + pidx);
    const float klv  = __ldg(g_kl + pidx);

    __shared__ unsigned char sfg[EW][56];  // fg halo: col cc = global j0-12+cc
    __shared__ unsigned char svv[TS][56];  // vertical min-d^2

    // fg halo: 52 rows x 14 aligned u32 words (single step, tid < 728)
    if (tid < EW * 14) {
        int r = tid / 14, k = tid - r * 14;
        int gi = i0 - RAD + r;
        int g0 = j0 - 12 + 4 * k;          // j0 % 32 == 0 -> g0 % 4 == 0
        unsigned int word = 0;
        if (gi >= 0 && gi < HH) {
            const unsigned char* rowp = g_fg + b * HW + gi * WW;
            if (g0 >= 0 && g0 + 3 < WW) {
                word = *(const unsigned int*)(rowp + g0);
            } else {
#pragma unroll
                for (int bb = 0; bb < 4; bb++) {
                    int gj = g0 + bb;
                    if (gj >= 0 && gj < WW)
                        word |= (unsigned int)rowp[gj] << (8 * bb);
                }
            }
        }
        *(unsigned int*)&sfg[r][4 * k] = word;
    }
    __syncthreads();

    // vertical 21-tap min, byte SIMD (term = 200 - fg*(200-d^2)), 2 chains
    if (tid < TS * 14) {
        int r = tid / 14, wc = (tid - r * 14) * 4;
        unsigned int va = 0xC8C8C8C8u, vb = 0xC8C8C8C8u;
#pragma unroll
        for (int dr = 0; dr < 21; dr += 2) {
            unsigned int f4 = *(const unsigned int*)&sfg[r + dr][wc];
            int d = dr - RAD;
            va = __vminu4(va, 0xC8C8C8C8u - f4 * (unsigned int)(200 - d * d));
        }
#pragma unroll
        for (int dr = 1; dr < 21; dr += 2) {
            unsigned int f4 = *(const unsigned int*)&sfg[r + dr][wc];
            int d = dr - RAD;
            vb = __vminu4(vb, 0xC8C8C8C8u - f4 * (unsigned int)(200 - d * d));
        }
        *(unsigned int*)&svv[r][wc] = __vminu4(va, vb);
    }
    __syncthreads();

    // horizontal 21-tap min: independent byte-LDS, 3 split chains
    // pixel col tx -> smem cc = tx+12; taps tx+2 .. tx+22
    int m0 = 300, m1 = 300, m2 = 300;
#pragma unroll
    for (int s = 0; s < 7; s++) {
        int dd = s - RAD;
        m0 = min(m0, dd * dd + (int)svv[ty][tx + 2 + s]);
    }
#pragma unroll
    for (int s = 7; s < 14; s++) {
        int dd = s - RAD;
        m1 = min(m1, dd * dd + (int)svv[ty][tx + 2 + s]);
    }
#pragma unroll
    for (int s = 14; s < 21; s++) {
        int dd = s - RAD;
        m2 = min(m2, dd * dd + (int)svv[ty][tx + 2 + s]);
    }
    const int d2 = min(m0, min(m1, m2));

    // base weight; conf = 1 - 0.9*ent/Em is linear in ent -> accumulate
    // A=Σbw·kl, B=Σbw·kl·ent, C=Σbw, D=Σbw·ent; Em applied at finalize.
    float a0 = 0.f, a1 = 0.f, a2 = 0.f, a3 = 0.f;
    if (d2 <= RAD * RAD) {
        float wd = __expf((float)d2 * (-1.0f / 50.0f));   // 2*sigma^2 = 50
        float bnd = 0.f;
        if (sfg[ty + RAD][tx + 12]) {
            bool er = sfg[ty + RAD - 1][tx + 12] && sfg[ty + RAD + 1][tx + 12]
                   && sfg[ty + RAD][tx + 11] && sfg[ty + RAD][tx + 13];
            if (!er) bnd = 1.f;
        }
        float bw = wd * (1.f + bnd);
        a0 = bw * klv;
        a1 = bw * klv * entv;
        a2 = bw;
        a3 = bw * entv;
    }

    // block reduce 4 sums
#pragma unroll
    for (int o = 16; o > 0; o >>= 1) {
        a0 += __shfl_xor_sync(0xFFFFFFFF, a0, o);
        a1 += __shfl_xor_sync(0xFFFFFFFF, a1, o);
        a2 += __shfl_xor_sync(0xFFFFFFFF, a2, o);
        a3 += __shfl_xor_sync(0xFFFFFFFF, a3, o);
    }
    __shared__ float red[4][32];
    if ((tid & 31) == 0) {
        red[0][tid >> 5] = a0; red[1][tid >> 5] = a1;
        red[2][tid >> 5] = a2; red[3][tid >> 5] = a3;
    }
    __syncthreads();

    __shared__ int s_fin;
    if (tid < 32) {
        float s0 = red[0][tid], s1 = red[1][tid], s2 = red[2][tid], s3 = red[3][tid];
#pragma unroll
        for (int o = 16; o > 0; o >>= 1) {
            s0 += __shfl_xor_sync(0xFFFFFFFF, s0, o);
            s1 += __shfl_xor_sync(0xFFFFFFFF, s1, o);
            s2 += __shfl_xor_sync(0xFFFFFFFF, s2, o);
            s3 += __shfl_xor_sync(0xFFFFFFFF, s3, o);
        }
        if (tid == 0) {
            g_part[gid] = make_float4(s0, s1, s2, s3);   // unique slot, no atomic
            __threadfence();                             // publish before counting
            s_fin = 0;
            unsigned int a = atomicAdd(&g_done1[gid >> 3], 1u);  // <=8 per address
            if (a == 7u) {
                unsigned int c = atomicAdd(&g_done2, 1u);        // 32 total
                if (c == 31u) s_fin = 1;
            }
        }
    }
    __syncthreads();

    // ---- elected last block: final reduction + output + counter reset ----
    if (s_fin) {
        __threadfence();   // acquire: all partials visible

        // per-image entropy max over 1024 K1 partials; warps 8b..8b+7 per image
        float v = g_entpart[tid];
#pragma unroll
        for (int o = 16; o > 0; o >>= 1)
            v = fmaxf(v, __shfl_xor_sync(0xFFFFFFFF, v, o));
        __shared__ float sEm[32];
        if ((tid & 31) == 0) sEm[tid >> 5] = v;
        __syncthreads();
        __shared__ float em[BB];
        if (tid < BB) {
            float m = sEm[tid * 8];
#pragma unroll
            for (int k = 1; k < 8; k++) m = fmaxf(m, sEm[tid * 8 + k]);
            em[tid] = m;
        }

        // sum 256 partial float4s; warps 2b, 2b+1 cover image b
        __shared__ double sacc[8][4];
        if (tid < 256) {
            float4 p = g_part[tid];
            float b0 = p.x, b1 = p.y, b2 = p.z, b3 = p.w;
#pragma unroll
            for (int o = 16; o > 0; o >>= 1) {
                b0 += __shfl_xor_sync(0xFFFFFFFF, b0, o);
                b1 += __shfl_xor_sync(0xFFFFFFFF, b1, o);
                b2 += __shfl_xor_sync(0xFFFFFFFF, b2, o);
                b3 += __shfl_xor_sync(0xFFFFFFFF, b3, o);
            }
            if ((tid & 31) == 0) {
                sacc[tid >> 5][0] = (double)b0;
                sacc[tid >> 5][1] = (double)b1;
                sacc[tid >> 5][2] = (double)b2;
                sacc[tid >> 5][3] = (double)b3;
            }
        }
        __syncthreads();

        if (tid == 0) {
            double num = 0.0, den = 0.0;
#pragma unroll
            for (int bb = 0; bb < BB; bb++) {
                double A  = sacc[2 * bb][0] + sacc[2 * bb + 1][0];
                double Bm = sacc[2 * bb][1] + sacc[2 * bb + 1][1];
                double Cc = sacc[2 * bb][2] + sacc[2 * bb + 1][2];
                double D  = sacc[2 * bb][3] + sacc[2 * bb + 1][3];
                double Em = (double)em[bb] + 1e-8;
                num += A - 0.9 * Bm / Em;
                den += Cc - 0.9 * D / Em;
            }
            out[0] = (float)(16.0 * num / (den + 1e-8));
            g_done2 = 0u;                  // reset for next graph replay
        }
        if (tid < 32) g_done1[tid] = 0u;
    }
}

extern "C" void kernel_launch(void* const* d_in, const int* in_sizes, int n_in,
                              void* d_out, int out_size)
{
    const float* student = (const float*)d_in[0];
    const float* teacher = (const float*)d_in[1];
    float* out = (float*)d_out;

    k1_channelwise<<<dim3(HW / 256, BB), 256>>>(student, teacher);
    k2_edt_weights<<<dim3(64, BB), 1024>>>(out);
}